// round 2
// baseline (speedup 1.0000x reference)
#include <cuda_runtime.h>

// SSIM loss: pred/target [16,3,512,512] f32. Separable 11-tap Gaussian,
// 5 fields (p, t, p*p, t*t, p*t), fused tile kernel + deterministic reduce.

#define TX   64      // output tile width
#define TY   32      // output tile height
#define LX   74      // loaded width  (TX + 10)
#define LY   42      // loaded height (TY + 10)
#define LXP  75      // padded row stride for input tiles (coprime with 32)
#define HSTR 65      // padded row stride for hpass tiles (coprime with 32)
#define GX   (512/TX)
#define GY   (512/TY)
#define GZ   48
#define NBLK (GX*GY*GZ)
#define NTOT 12582912.0   // 16*3*512*512

// Gaussian(sigma=1.5, 11 taps), normalized. constexpr accessor so every
// fully-unrolled call folds to a literal -> FFMA with immediate multiplier
// (rt_SMSP = 1 -> 2x FFMA throughput vs 3-reg form).
__host__ __device__ constexpr float GWc(int k) {
    return (k == 0) ? 0.00102838f
         : (k == 1) ? 0.00759875f
         : (k == 2) ? 0.03600077f
         : (k == 3) ? 0.10936070f
         : (k == 4) ? 0.21300553f
         : (k == 5) ? 0.26601172f
         : (k == 6) ? 0.21300553f
         : (k == 7) ? 0.10936070f
         : (k == 8) ? 0.03600077f
         : (k == 9) ? 0.00759875f
         :            0.00102838f;
}

__device__ float g_partials[NBLK];

__global__ void __launch_bounds__(256, 2)
ssim_tile_kernel(const float* __restrict__ pred, const float* __restrict__ targ)
{
    extern __shared__ float smem[];
    float* sp = smem;                 // LY*LXP   pred tile
    float* st = smem + LY * LXP;      // LY*LXP   target tile
    float* sh = smem + 2 * LY * LXP;  // 5 * LY * HSTR  hpass results

    const int tid = threadIdx.x;
    const int x0 = blockIdx.x * TX;
    const int y0 = blockIdx.y * TY;
    const int plane = blockIdx.z * (512 * 512);
    const float* pb = pred + plane;
    const float* tb = targ + plane;

    // ---- Load pred/target tile with halo (zero pad outside image) ----
    for (int i = tid; i < LY * LX; i += 256) {
        int r = i / LX;
        int c = i - r * LX;
        int gy = y0 - 5 + r;
        int gx = x0 - 5 + c;
        bool ok = ((unsigned)gy < 512u) && ((unsigned)gx < 512u);
        float pv = ok ? __ldg(pb + gy * 512 + gx) : 0.0f;
        float tv = ok ? __ldg(tb + gy * 512 + gx) : 0.0f;
        sp[r * LXP + c] = pv;
        st[r * LXP + c] = tv;
    }
    __syncthreads();

    // ---- Horizontal pass: 420 tasks = 2 halves x 5 fields x 42 rows ----
    // Each task streams a 42-wide row segment through registers (sliding
    // window), produces 32 horizontally-convolved outputs.
    for (int t = tid; t < 420; t += 256) {
        int half = (t >= 210) ? 1 : 0;
        int rem  = t - half * 210;
        int f    = rem / 42;
        int r    = rem - f * 42;
        int cb   = half * 32;

        const float* prow = sp + r * LXP + cb;
        const float* trow = st + r * LXP + cb;

        float xv[42];
        if (f == 0) {
            #pragma unroll
            for (int j = 0; j < 42; j++) xv[j] = prow[j];
        } else if (f == 1) {
            #pragma unroll
            for (int j = 0; j < 42; j++) xv[j] = trow[j];
        } else if (f == 2) {
            #pragma unroll
            for (int j = 0; j < 42; j++) { float v = prow[j]; xv[j] = v * v; }
        } else if (f == 3) {
            #pragma unroll
            for (int j = 0; j < 42; j++) { float v = trow[j]; xv[j] = v * v; }
        } else {
            #pragma unroll
            for (int j = 0; j < 42; j++) xv[j] = prow[j] * trow[j];
        }

        float* orow = sh + f * (LY * HSTR) + r * HSTR + cb;
        #pragma unroll
        for (int o = 0; o < 32; o++) {
            float a = GWc(0) * xv[o];
            #pragma unroll
            for (int k = 1; k < 11; k++) a = fmaf(GWc(k), xv[o + k], a);
            orow[o] = a;
        }
    }
    __syncthreads();

    // ---- Vertical pass + SSIM map: thread = (column x, 8-row strip) ----
    const int x  = tid & 63;
    const int r0 = (tid >> 6) * 8;

    float acc[5][8];
    #pragma unroll
    for (int f = 0; f < 5; f++) {
        const float* col = sh + f * (LY * HSTR) + r0 * HSTR + x;
        float w[18];
        #pragma unroll
        for (int j = 0; j < 18; j++) w[j] = col[j * HSTR];
        #pragma unroll
        for (int o = 0; o < 8; o++) {
            float a = GWc(0) * w[o];
            #pragma unroll
            for (int k = 1; k < 11; k++) a = fmaf(GWc(k), w[o + k], a);
            acc[f][o] = a;
        }
    }

    const float C1 = 0.0001f;   // 0.01^2
    const float C2 = 0.0009f;   // 0.03^2
    float lsum = 0.0f;
    #pragma unroll
    for (int o = 0; o < 8; o++) {
        float mu1 = acc[0][o], mu2 = acc[1][o];
        float mu1sq = mu1 * mu1;
        float mu2sq = mu2 * mu2;
        float mu12  = mu1 * mu2;
        float s1  = acc[2][o] - mu1sq;
        float s2  = acc[3][o] - mu2sq;
        float s12 = acc[4][o] - mu12;
        float num = (2.0f * mu12 + C1) * (2.0f * s12 + C2);
        float den = (mu1sq + mu2sq + C1) * (s1 + s2 + C2);
        lsum += num / den;
    }

    // ---- Block reduction (deterministic: fixed shuffle tree + ordered sum) ----
    #pragma unroll
    for (int off = 16; off > 0; off >>= 1)
        lsum += __shfl_down_sync(0xffffffffu, lsum, off);
    if ((tid & 31) == 0) smem[tid >> 5] = lsum;   // sp region is dead here
    __syncthreads();
    if (tid == 0) {
        float tot = 0.0f;
        #pragma unroll
        for (int wpi = 0; wpi < 8; wpi++) tot += smem[wpi];
        int bidx = (blockIdx.z * gridDim.y + blockIdx.y) * gridDim.x + blockIdx.x;
        g_partials[bidx] = tot;
    }
}

__global__ void ssim_finalize(float* __restrict__ out)
{
    __shared__ double shr[8];
    double s = 0.0;
    for (int i = threadIdx.x; i < NBLK; i += 256)
        s += (double)g_partials[i];
    #pragma unroll
    for (int off = 16; off > 0; off >>= 1)
        s += __shfl_down_sync(0xffffffffu, s, off);
    if ((threadIdx.x & 31) == 0) shr[threadIdx.x >> 5] = s;
    __syncthreads();
    if (threadIdx.x == 0) {
        double tot = 0.0;
        #pragma unroll
        for (int w = 0; w < 8; w++) tot += shr[w];
        out[0] = (float)(1.0 - tot / NTOT);
    }
}

extern "C" void kernel_launch(void* const* d_in, const int* in_sizes, int n_in,
                              void* d_out, int out_size)
{
    const float* pred = (const float*)d_in[0];
    const float* targ = (const float*)d_in[1];
    float* out = (float*)d_out;

    constexpr int smem_bytes = (2 * LY * LXP + 5 * LY * HSTR) * (int)sizeof(float);
    cudaFuncSetAttribute(ssim_tile_kernel,
                         cudaFuncAttributeMaxDynamicSharedMemorySize, smem_bytes);

    dim3 grid(GX, GY, GZ);
    ssim_tile_kernel<<<grid, 256, smem_bytes>>>(pred, targ);
    ssim_finalize<<<1, 256>>>(out);
}

// round 3
// speedup vs baseline: 1.0989x; 1.0989x over previous
#include <cuda_runtime.h>

// SSIM loss, pred/target [16,3,512,512] f32.
// Separable 11-tap Gaussian; fields packed 2-wide for fma.rn.f32x2:
//   stream A: (p, t)      packed in .x/.y
//   stream B: (p*p, t*t)  packed
//   stream C: p*t packed across row-pairs (r, r+21)
// Fused tile kernel (64x32 out, 74x42 loaded) + deterministic reduce.

#define TX   64
#define TY   32
#define LX   74
#define LY   42
#define SPW  75      // spt row stride (u64 units); lane-row delta 150 words -> conflict-free halves
#define CS   43      // shA/shB column stride (u64); lane-col delta 86 words -> conflict-free halves
#define CSS  45      // shC column stride (f32); delta 45 words (odd) -> conflict-free
#define GX   (512/TX)
#define GY   (512/TY)
#define GZ   48
#define NBLK (GX*GY*GZ)
#define NTOT 12582912.0

using u64 = unsigned long long;

__host__ __device__ constexpr float GWc(int k) {
    return (k == 0) ? 0.00102838f
         : (k == 1) ? 0.00759875f
         : (k == 2) ? 0.03600077f
         : (k == 3) ? 0.10936070f
         : (k == 4) ? 0.21300553f
         : (k == 5) ? 0.26601172f
         : (k == 6) ? 0.21300553f
         : (k == 7) ? 0.10936070f
         : (k == 8) ? 0.03600077f
         : (k == 9) ? 0.00759875f
         :            0.00102838f;
}

__device__ __forceinline__ u64 pack2(float lo, float hi) {
    u64 r; asm("mov.b64 %0, {%1,%2};" : "=l"(r) : "f"(lo), "f"(hi)); return r;
}
__device__ __forceinline__ void unpack2(u64 v, float& lo, float& hi) {
    asm("mov.b64 {%0,%1}, %2;" : "=f"(lo), "=f"(hi) : "l"(v));
}
__device__ __forceinline__ u64 fma2(u64 a, u64 b, u64 c) {
    u64 r; asm("fma.rn.f32x2 %0, %1, %2, %3;" : "=l"(r) : "l"(a), "l"(b), "l"(c)); return r;
}
__device__ __forceinline__ u64 mul2(u64 a, u64 b) {
    u64 r; asm("mul.rn.f32x2 %0, %1, %2;" : "=l"(r) : "l"(a), "l"(b)); return r;
}

__device__ float g_partials[NBLK];

__global__ void __launch_bounds__(256, 2)
ssim_tile_kernel(const float* __restrict__ pred, const float* __restrict__ targ)
{
    extern __shared__ char smem_raw[];
    u64*   spt  = (u64*)smem_raw;              // LY*SPW  (p,t) pairs
    u64*   shA  = spt + LY * SPW;              // 64*CS   hpass (mu1h, mu2h), [col][row]
    u64*   shB  = shA + 64 * CS;               // 64*CS   hpass (p2h, t2h),  [col][row]
    float* shC  = (float*)(shB + 64 * CS);     // 64*CSS  hpass pt, [col][row]
    float* sred = shC + 64 * CSS;              // 8 floats, reduction scratch

    const int tid = threadIdx.x;
    const int x0 = blockIdx.x * TX;
    const int y0 = blockIdx.y * TY;
    const int plane = blockIdx.z * (512 * 512);
    const float* pb = pred + plane;
    const float* tb = targ + plane;

    // ---- Load tile with halo, interleave (p,t) into u64 ----
    for (int i = tid; i < LY * LX; i += 256) {
        int r = i / LX;
        int c = i - r * LX;
        int gy = y0 - 5 + r;
        int gx = x0 - 5 + c;
        bool ok = ((unsigned)gy < 512u) && ((unsigned)gx < 512u);
        float pv = ok ? __ldg(pb + gy * 512 + gx) : 0.0f;
        float tv = ok ? __ldg(tb + gy * 512 + gx) : 0.0f;
        spt[r * SPW + c] = pack2(pv, tv);
    }
    __syncthreads();

    // packed weights (duplicated lanes); symmetric -> compiler CSEs to 6 live regs
    u64 wp[11];
    #pragma unroll
    for (int k = 0; k < 11; k++) wp[k] = pack2(GWc(k), GWc(k));

    // ---- Horizontal pass, warp-pure stream assignment ----
    // warps 0-2: stream A (84 tasks)   warps 3-5: stream B (84 tasks)
    // warps 6-7: stream C (42 tasks, row-pairs)
    const int w = tid >> 5;
    if (w < 3) {
        int t = tid;
        if (t < 84) {
            int half = (t >= 42); int r = t - half * 42; int cb = half * 32;
            const u64* row = spt + r * SPW + cb;
            u64 acc[32];
            #pragma unroll
            for (int o = 0; o < 32; o++) acc[o] = 0ull;
            #pragma unroll
            for (int j = 0; j < 42; j++) {
                u64 x = row[j];
                #pragma unroll
                for (int k = 0; k < 11; k++) {
                    int o = j - k;
                    if (o >= 0 && o < 32) acc[o] = fma2(wp[k], x, acc[o]);
                }
            }
            u64* out = shA + r;
            #pragma unroll
            for (int o = 0; o < 32; o++) out[(cb + o) * CS] = acc[o];
        }
    } else if (w < 6) {
        int t = tid - 96;
        if (t < 84) {
            int half = (t >= 42); int r = t - half * 42; int cb = half * 32;
            const u64* row = spt + r * SPW + cb;
            u64 acc[32];
            #pragma unroll
            for (int o = 0; o < 32; o++) acc[o] = 0ull;
            #pragma unroll
            for (int j = 0; j < 42; j++) {
                u64 x = row[j];
                x = mul2(x, x);
                #pragma unroll
                for (int k = 0; k < 11; k++) {
                    int o = j - k;
                    if (o >= 0 && o < 32) acc[o] = fma2(wp[k], x, acc[o]);
                }
            }
            u64* out = shB + r;
            #pragma unroll
            for (int o = 0; o < 32; o++) out[(cb + o) * CS] = acc[o];
        }
    } else {
        int t = tid - 192;
        if (t < 42) {
            int half = (t >= 21); int rp = t - half * 21; int cb = half * 32;
            int r0 = rp, r1 = rp + 21;
            const u64* rowa = spt + r0 * SPW + cb;
            const u64* rowb = spt + r1 * SPW + cb;
            u64 acc[32];
            #pragma unroll
            for (int o = 0; o < 32; o++) acc[o] = 0ull;
            #pragma unroll
            for (int j = 0; j < 42; j++) {
                float pa, ta, pc, tc;
                unpack2(rowa[j], pa, ta);
                unpack2(rowb[j], pc, tc);
                u64 x = pack2(pa * ta, pc * tc);
                #pragma unroll
                for (int k = 0; k < 11; k++) {
                    int o = j - k;
                    if (o >= 0 && o < 32) acc[o] = fma2(wp[k], x, acc[o]);
                }
            }
            #pragma unroll
            for (int o = 0; o < 32; o++) {
                float va, vb;
                unpack2(acc[o], va, vb);
                shC[(cb + o) * CSS + r0] = va;
                shC[(cb + o) * CSS + r1] = vb;
            }
        }
    }
    __syncthreads();

    // ---- Vertical pass + SSIM: thread = (column x, 8-row strip) ----
    const int x  = tid & 63;
    const int r0 = (tid >> 6) * 8;

    u64 mu[8];
    {
        const u64* col = shA + x * CS + r0;
        u64 wv[18];
        #pragma unroll
        for (int j = 0; j < 18; j++) wv[j] = col[j];
        #pragma unroll
        for (int o = 0; o < 8; o++) {
            u64 a = mul2(wp[0], wv[o]);
            #pragma unroll
            for (int k = 1; k < 11; k++) a = fma2(wp[k], wv[o + k], a);
            mu[o] = a;
        }
    }
    u64 sq[8];
    {
        const u64* col = shB + x * CS + r0;
        u64 wv[18];
        #pragma unroll
        for (int j = 0; j < 18; j++) wv[j] = col[j];
        #pragma unroll
        for (int o = 0; o < 8; o++) {
            u64 a = mul2(wp[0], wv[o]);
            #pragma unroll
            for (int k = 1; k < 11; k++) a = fma2(wp[k], wv[o + k], a);
            sq[o] = a;
        }
    }
    float cpt[8];
    {
        const float* col = shC + x * CSS + r0;
        float wc[18];
        #pragma unroll
        for (int j = 0; j < 18; j++) wc[j] = col[j];
        u64 pw[14];
        #pragma unroll
        for (int j = 0; j < 14; j++) pw[j] = pack2(wc[j], wc[j + 4]);
        #pragma unroll
        for (int o = 0; o < 4; o++) {
            u64 a = mul2(wp[0], pw[o]);
            #pragma unroll
            for (int k = 1; k < 11; k++) a = fma2(wp[k], pw[o + k], a);
            unpack2(a, cpt[o], cpt[o + 4]);   // outputs o and o+4
        }
    }

    const float C1 = 0.0001f;
    const float C2 = 0.0009f;
    float lsum = 0.0f;
    #pragma unroll
    for (int o = 0; o < 8; o++) {
        float mu1, mu2, ep2, et2;
        unpack2(mu[o], mu1, mu2);
        unpack2(sq[o], ep2, et2);
        float mu1sq = mu1 * mu1;
        float mu2sq = mu2 * mu2;
        float mu12  = mu1 * mu2;
        float s1  = ep2 - mu1sq;
        float s2  = et2 - mu2sq;
        float s12 = cpt[o] - mu12;
        float num = (2.0f * mu12 + C1) * (2.0f * s12 + C2);
        float den = (mu1sq + mu2sq + C1) * (s1 + s2 + C2);
        lsum += __fdividef(num, den);
    }

    // ---- Deterministic block reduction ----
    #pragma unroll
    for (int off = 16; off > 0; off >>= 1)
        lsum += __shfl_down_sync(0xffffffffu, lsum, off);
    if ((tid & 31) == 0) sred[tid >> 5] = lsum;
    __syncthreads();
    if (tid == 0) {
        float tot = 0.0f;
        #pragma unroll
        for (int wi = 0; wi < 8; wi++) tot += sred[wi];
        int bidx = (blockIdx.z * gridDim.y + blockIdx.y) * gridDim.x + blockIdx.x;
        g_partials[bidx] = tot;
    }
}

__global__ void __launch_bounds__(1024, 1)
ssim_finalize(float* __restrict__ out)
{
    __shared__ double shr[32];
    const int tid = threadIdx.x;
    double s = 0.0;
    for (int i = tid; i < NBLK; i += 1024)
        s += (double)g_partials[i];
    #pragma unroll
    for (int off = 16; off > 0; off >>= 1)
        s += __shfl_down_sync(0xffffffffu, s, off);
    if ((tid & 31) == 0) shr[tid >> 5] = s;
    __syncthreads();
    if (tid == 0) {
        double tot = 0.0;
        #pragma unroll
        for (int w = 0; w < 32; w++) tot += shr[w];
        out[0] = (float)(1.0 - tot / NTOT);
    }
}

extern "C" void kernel_launch(void* const* d_in, const int* in_sizes, int n_in,
                              void* d_out, int out_size)
{
    const float* pred = (const float*)d_in[0];
    const float* targ = (const float*)d_in[1];
    float* out = (float*)d_out;

    constexpr int smem_bytes =
        (LY * SPW + 2 * 64 * CS) * 8 + 64 * CSS * 4 + 8 * 4;
    cudaFuncSetAttribute(ssim_tile_kernel,
                         cudaFuncAttributeMaxDynamicSharedMemorySize, smem_bytes);

    dim3 grid(GX, GY, GZ);
    ssim_tile_kernel<<<grid, 256, smem_bytes>>>(pred, targ);
    ssim_finalize<<<1, 1024>>>(out);
}

// round 5
// speedup vs baseline: 1.1075x; 1.0078x over previous
#include <cuda_runtime.h>

// SSIM loss, pred/target [16,3,512,512] f32.
// Separable 11-tap Gaussian; fields packed 2-wide for fma.rn.f32x2:
//   stream A: (p, t)      packed in .x/.y
//   stream B: (p*p, t*t)  packed
//   stream C: p*t packed across row-pairs (r, r+21)
// Fused tile kernel (64x32 out, 74x42 loaded) + deterministic reduce.

#define TX   64
#define TY   32
#define LX   74
#define LY   42
#define SPW  75      // spt row stride (u64 units); lane-row delta 150 words -> conflict-free halves
#define CS   43      // shA/shB column stride (u64); lane-col delta 86 words -> conflict-free halves
#define CSS  45      // shC column stride (f32); delta 45 words (odd) -> conflict-free
#define GX   (512/TX)
#define GY   (512/TY)
#define GZ   48
#define NBLK (GX*GY*GZ)
#define NTOT 12582912.0

using u64 = unsigned long long;

__host__ __device__ constexpr float GWc(int k) {
    return (k == 0) ? 0.00102838f
         : (k == 1) ? 0.00759875f
         : (k == 2) ? 0.03600077f
         : (k == 3) ? 0.10936070f
         : (k == 4) ? 0.21300553f
         : (k == 5) ? 0.26601172f
         : (k == 6) ? 0.21300553f
         : (k == 7) ? 0.10936070f
         : (k == 8) ? 0.03600077f
         : (k == 9) ? 0.00759875f
         :            0.00102838f;
}

__device__ __forceinline__ u64 pack2(float lo, float hi) {
    u64 r; asm("mov.b64 %0, {%1,%2};" : "=l"(r) : "f"(lo), "f"(hi)); return r;
}
__device__ __forceinline__ void unpack2(u64 v, float& lo, float& hi) {
    asm("mov.b64 {%0,%1}, %2;" : "=f"(lo), "=f"(hi) : "l"(v));
}
__device__ __forceinline__ u64 fma2(u64 a, u64 b, u64 c) {
    u64 r; asm("fma.rn.f32x2 %0, %1, %2, %3;" : "=l"(r) : "l"(a), "l"(b), "l"(c)); return r;
}
__device__ __forceinline__ u64 mul2(u64 a, u64 b) {
    u64 r; asm("mul.rn.f32x2 %0, %1, %2;" : "=l"(r) : "l"(a), "l"(b)); return r;
}

__device__ float g_partials[NBLK];

__global__ void __launch_bounds__(256, 2)
ssim_tile_kernel(const float* __restrict__ pred, const float* __restrict__ targ)
{
    extern __shared__ char smem_raw[];
    u64*   spt  = (u64*)smem_raw;              // LY*SPW  (p,t) pairs
    u64*   shA  = spt + LY * SPW;              // 64*CS   hpass (mu1h, mu2h), [col][row]
    u64*   shB  = shA + 64 * CS;               // 64*CS   hpass (p2h, t2h),  [col][row]
    float* shC  = (float*)(shB + 64 * CS);     // 64*CSS  hpass pt, [col][row]
    float* sred = shC + 64 * CSS;              // 8 floats, reduction scratch

    const int tid = threadIdx.x;
    const int x0 = blockIdx.x * TX;
    const int y0 = blockIdx.y * TY;
    const int plane = blockIdx.z * (512 * 512);
    const float* pb = pred + plane;
    const float* tb = targ + plane;

    // ---- Load tile with halo, interleave (p,t) into u64 ----
    for (int i = tid; i < LY * LX; i += 256) {
        int r = i / LX;
        int c = i - r * LX;
        int gy = y0 - 5 + r;
        int gx = x0 - 5 + c;
        bool ok = ((unsigned)gy < 512u) && ((unsigned)gx < 512u);
        float pv = ok ? __ldg(pb + gy * 512 + gx) : 0.0f;
        float tv = ok ? __ldg(tb + gy * 512 + gx) : 0.0f;
        spt[r * SPW + c] = pack2(pv, tv);
    }
    __syncthreads();

    // packed weights (duplicated lanes); symmetric -> compiler CSEs to 6 live regs
    u64 wp[11];
    #pragma unroll
    for (int k = 0; k < 11; k++) wp[k] = pack2(GWc(k), GWc(k));

    // ---- Horizontal pass, warp-pure stream assignment ----
    // warps 0-2: stream A (84 tasks)   warps 3-5: stream B (84 tasks)
    // warps 6-7: stream C (42 tasks, row-pairs)
    const int w = tid >> 5;
    if (w < 3) {
        int t = tid;
        if (t < 84) {
            int half = (t >= 42); int r = t - half * 42; int cb = half * 32;
            const u64* row = spt + r * SPW + cb;
            u64 acc[32];
            #pragma unroll
            for (int o = 0; o < 32; o++) acc[o] = 0ull;
            #pragma unroll
            for (int j = 0; j < 42; j++) {
                u64 x = row[j];
                #pragma unroll
                for (int k = 0; k < 11; k++) {
                    int o = j - k;
                    if (o >= 0 && o < 32) acc[o] = fma2(wp[k], x, acc[o]);
                }
            }
            u64* out = shA + r;
            #pragma unroll
            for (int o = 0; o < 32; o++) out[(cb + o) * CS] = acc[o];
        }
    } else if (w < 6) {
        int t = tid - 96;
        if (t < 84) {
            int half = (t >= 42); int r = t - half * 42; int cb = half * 32;
            const u64* row = spt + r * SPW + cb;
            u64 acc[32];
            #pragma unroll
            for (int o = 0; o < 32; o++) acc[o] = 0ull;
            #pragma unroll
            for (int j = 0; j < 42; j++) {
                u64 x = row[j];
                x = mul2(x, x);
                #pragma unroll
                for (int k = 0; k < 11; k++) {
                    int o = j - k;
                    if (o >= 0 && o < 32) acc[o] = fma2(wp[k], x, acc[o]);
                }
            }
            u64* out = shB + r;
            #pragma unroll
            for (int o = 0; o < 32; o++) out[(cb + o) * CS] = acc[o];
        }
    } else {
        int t = tid - 192;
        if (t < 42) {
            int half = (t >= 21); int rp = t - half * 21; int cb = half * 32;
            int r0 = rp, r1 = rp + 21;
            const u64* rowa = spt + r0 * SPW + cb;
            const u64* rowb = spt + r1 * SPW + cb;
            u64 acc[32];
            #pragma unroll
            for (int o = 0; o < 32; o++) acc[o] = 0ull;
            #pragma unroll
            for (int j = 0; j < 42; j++) {
                float pa, ta, pc, tc;
                unpack2(rowa[j], pa, ta);
                unpack2(rowb[j], pc, tc);
                u64 x = pack2(pa * ta, pc * tc);
                #pragma unroll
                for (int k = 0; k < 11; k++) {
                    int o = j - k;
                    if (o >= 0 && o < 32) acc[o] = fma2(wp[k], x, acc[o]);
                }
            }
            #pragma unroll
            for (int o = 0; o < 32; o++) {
                float va, vb;
                unpack2(acc[o], va, vb);
                shC[(cb + o) * CSS + r0] = va;
                shC[(cb + o) * CSS + r1] = vb;
            }
        }
    }
    __syncthreads();

    // ---- Vertical pass + SSIM: thread = (column x, 8-row strip) ----
    const int x  = tid & 63;
    const int r0 = (tid >> 6) * 8;

    u64 mu[8];
    {
        const u64* col = shA + x * CS + r0;
        u64 wv[18];
        #pragma unroll
        for (int j = 0; j < 18; j++) wv[j] = col[j];
        #pragma unroll
        for (int o = 0; o < 8; o++) {
            u64 a = mul2(wp[0], wv[o]);
            #pragma unroll
            for (int k = 1; k < 11; k++) a = fma2(wp[k], wv[o + k], a);
            mu[o] = a;
        }
    }
    u64 sq[8];
    {
        const u64* col = shB + x * CS + r0;
        u64 wv[18];
        #pragma unroll
        for (int j = 0; j < 18; j++) wv[j] = col[j];
        #pragma unroll
        for (int o = 0; o < 8; o++) {
            u64 a = mul2(wp[0], wv[o]);
            #pragma unroll
            for (int k = 1; k < 11; k++) a = fma2(wp[k], wv[o + k], a);
            sq[o] = a;
        }
    }
    float cpt[8];
    {
        const float* col = shC + x * CSS + r0;
        float wc[18];
        #pragma unroll
        for (int j = 0; j < 18; j++) wc[j] = col[j];
        u64 pw[14];
        #pragma unroll
        for (int j = 0; j < 14; j++) pw[j] = pack2(wc[j], wc[j + 4]);
        #pragma unroll
        for (int o = 0; o < 4; o++) {
            u64 a = mul2(wp[0], pw[o]);
            #pragma unroll
            for (int k = 1; k < 11; k++) a = fma2(wp[k], pw[o + k], a);
            unpack2(a, cpt[o], cpt[o + 4]);   // outputs o and o+4
        }
    }

    const float C1 = 0.0001f;
    const float C2 = 0.0009f;
    float lsum = 0.0f;
    #pragma unroll
    for (int o = 0; o < 8; o++) {
        float mu1, mu2, ep2, et2;
        unpack2(mu[o], mu1, mu2);
        unpack2(sq[o], ep2, et2);
        float mu1sq = mu1 * mu1;
        float mu2sq = mu2 * mu2;
        float mu12  = mu1 * mu2;
        float s1  = ep2 - mu1sq;
        float s2  = et2 - mu2sq;
        float s12 = cpt[o] - mu12;
        float num = (2.0f * mu12 + C1) * (2.0f * s12 + C2);
        float den = (mu1sq + mu2sq + C1) * (s1 + s2 + C2);
        lsum += __fdividef(num, den);
    }

    // ---- Deterministic block reduction ----
    #pragma unroll
    for (int off = 16; off > 0; off >>= 1)
        lsum += __shfl_down_sync(0xffffffffu, lsum, off);
    if ((tid & 31) == 0) sred[tid >> 5] = lsum;
    __syncthreads();
    if (tid == 0) {
        float tot = 0.0f;
        #pragma unroll
        for (int wi = 0; wi < 8; wi++) tot += sred[wi];
        int bidx = (blockIdx.z * gridDim.y + blockIdx.y) * gridDim.x + blockIdx.x;
        g_partials[bidx] = tot;
    }
}

__global__ void __launch_bounds__(1024, 1)
ssim_finalize(float* __restrict__ out)
{
    __shared__ double shr[32];
    const int tid = threadIdx.x;
    double s = 0.0;
    for (int i = tid; i < NBLK; i += 1024)
        s += (double)g_partials[i];
    #pragma unroll
    for (int off = 16; off > 0; off >>= 1)
        s += __shfl_down_sync(0xffffffffu, s, off);
    if ((tid & 31) == 0) shr[tid >> 5] = s;
    __syncthreads();
    if (tid == 0) {
        double tot = 0.0;
        #pragma unroll
        for (int w = 0; w < 32; w++) tot += shr[w];
        out[0] = (float)(1.0 - tot / NTOT);
    }
}

extern "C" void kernel_launch(void* const* d_in, const int* in_sizes, int n_in,
                              void* d_out, int out_size)
{
    const float* pred = (const float*)d_in[0];
    const float* targ = (const float*)d_in[1];
    float* out = (float*)d_out;

    constexpr int smem_bytes =
        (LY * SPW + 2 * 64 * CS) * 8 + 64 * CSS * 4 + 8 * 4;
    cudaFuncSetAttribute(ssim_tile_kernel,
                         cudaFuncAttributeMaxDynamicSharedMemorySize, smem_bytes);

    dim3 grid(GX, GY, GZ);
    ssim_tile_kernel<<<grid, 256, smem_bytes>>>(pred, targ);
    ssim_finalize<<<1, 1024>>>(out);
}

// round 6
// speedup vs baseline: 1.1086x; 1.0010x over previous
#include <cuda_runtime.h>

// SSIM loss, pred/target [16,3,512,512] f32.
// Separable 11-tap Gaussian; fields packed 2-wide for fma.rn.f32x2:
//   stream A: (p, t)      packed in .x/.y
//   stream B: (p*p, t*t)  packed
//   stream C: p*t packed across row-pairs (r, r+21)
// Fused tile kernel (64x32 out, 74x42 loaded) + deterministic reduce.

#define TX   64
#define TY   32
#define LX   74
#define LY   42
#define SPW  75      // spt row stride (u64 units); lane-row delta 150 words -> conflict-free halves
#define CS   43      // shA/shB column stride (u64); lane-col delta 86 words -> conflict-free halves
#define CSS  45      // shC column stride (f32); delta 45 words (odd) -> conflict-free
#define GX   (512/TX)
#define GY   (512/TY)
#define GZ   48
#define NBLK (GX*GY*GZ)
#define NTOT 12582912.0

using u64 = unsigned long long;

__host__ __device__ constexpr float GWc(int k) {
    return (k == 0) ? 0.00102838f
         : (k == 1) ? 0.00759875f
         : (k == 2) ? 0.03600077f
         : (k == 3) ? 0.10936070f
         : (k == 4) ? 0.21300553f
         : (k == 5) ? 0.26601172f
         : (k == 6) ? 0.21300553f
         : (k == 7) ? 0.10936070f
         : (k == 8) ? 0.03600077f
         : (k == 9) ? 0.00759875f
         :            0.00102838f;
}

__device__ __forceinline__ u64 pack2(float lo, float hi) {
    u64 r; asm("mov.b64 %0, {%1,%2};" : "=l"(r) : "f"(lo), "f"(hi)); return r;
}
__device__ __forceinline__ void unpack2(u64 v, float& lo, float& hi) {
    asm("mov.b64 {%0,%1}, %2;" : "=f"(lo), "=f"(hi) : "l"(v));
}
__device__ __forceinline__ u64 fma2(u64 a, u64 b, u64 c) {
    u64 r; asm("fma.rn.f32x2 %0, %1, %2, %3;" : "=l"(r) : "l"(a), "l"(b), "l"(c)); return r;
}
__device__ __forceinline__ u64 mul2(u64 a, u64 b) {
    u64 r; asm("mul.rn.f32x2 %0, %1, %2;" : "=l"(r) : "l"(a), "l"(b)); return r;
}

__device__ float g_partials[NBLK];

__global__ void __launch_bounds__(256, 2)
ssim_tile_kernel(const float* __restrict__ pred, const float* __restrict__ targ)
{
    extern __shared__ char smem_raw[];
    u64*   spt  = (u64*)smem_raw;              // LY*SPW  (p,t) pairs
    u64*   shA  = spt + LY * SPW;              // 64*CS   hpass (mu1h, mu2h), [col][row]
    u64*   shB  = shA + 64 * CS;               // 64*CS   hpass (p2h, t2h),  [col][row]
    float* shC  = (float*)(shB + 64 * CS);     // 64*CSS  hpass pt, [col][row]
    float* sred = shC + 64 * CSS;              // 8 floats, reduction scratch

    const int tid = threadIdx.x;
    const int x0 = blockIdx.x * TX;
    const int y0 = blockIdx.y * TY;
    const int plane = blockIdx.z * (512 * 512);
    const float* pb = pred + plane;
    const float* tb = targ + plane;

    // ---- Load tile with halo, interleave (p,t) into u64 ----
    for (int i = tid; i < LY * LX; i += 256) {
        int r = i / LX;
        int c = i - r * LX;
        int gy = y0 - 5 + r;
        int gx = x0 - 5 + c;
        bool ok = ((unsigned)gy < 512u) && ((unsigned)gx < 512u);
        float pv = ok ? __ldg(pb + gy * 512 + gx) : 0.0f;
        float tv = ok ? __ldg(tb + gy * 512 + gx) : 0.0f;
        spt[r * SPW + c] = pack2(pv, tv);
    }
    __syncthreads();

    // packed weights (duplicated lanes); symmetric -> compiler CSEs to 6 live regs
    u64 wp[11];
    #pragma unroll
    for (int k = 0; k < 11; k++) wp[k] = pack2(GWc(k), GWc(k));

    // ---- Horizontal pass, warp-pure stream assignment ----
    // warps 0-2: stream A (84 tasks)   warps 3-5: stream B (84 tasks)
    // warps 6-7: stream C (42 tasks, row-pairs)
    const int w = tid >> 5;
    if (w < 3) {
        int t = tid;
        if (t < 84) {
            int half = (t >= 42); int r = t - half * 42; int cb = half * 32;
            const u64* row = spt + r * SPW + cb;
            u64 acc[32];
            #pragma unroll
            for (int o = 0; o < 32; o++) acc[o] = 0ull;
            #pragma unroll
            for (int j = 0; j < 42; j++) {
                u64 x = row[j];
                #pragma unroll
                for (int k = 0; k < 11; k++) {
                    int o = j - k;
                    if (o >= 0 && o < 32) acc[o] = fma2(wp[k], x, acc[o]);
                }
            }
            u64* out = shA + r;
            #pragma unroll
            for (int o = 0; o < 32; o++) out[(cb + o) * CS] = acc[o];
        }
    } else if (w < 6) {
        int t = tid - 96;
        if (t < 84) {
            int half = (t >= 42); int r = t - half * 42; int cb = half * 32;
            const u64* row = spt + r * SPW + cb;
            u64 acc[32];
            #pragma unroll
            for (int o = 0; o < 32; o++) acc[o] = 0ull;
            #pragma unroll
            for (int j = 0; j < 42; j++) {
                u64 x = row[j];
                x = mul2(x, x);
                #pragma unroll
                for (int k = 0; k < 11; k++) {
                    int o = j - k;
                    if (o >= 0 && o < 32) acc[o] = fma2(wp[k], x, acc[o]);
                }
            }
            u64* out = shB + r;
            #pragma unroll
            for (int o = 0; o < 32; o++) out[(cb + o) * CS] = acc[o];
        }
    } else {
        int t = tid - 192;
        if (t < 42) {
            int half = (t >= 21); int rp = t - half * 21; int cb = half * 32;
            int r0 = rp, r1 = rp + 21;
            const u64* rowa = spt + r0 * SPW + cb;
            const u64* rowb = spt + r1 * SPW + cb;
            u64 acc[32];
            #pragma unroll
            for (int o = 0; o < 32; o++) acc[o] = 0ull;
            #pragma unroll
            for (int j = 0; j < 42; j++) {
                float pa, ta, pc, tc;
                unpack2(rowa[j], pa, ta);
                unpack2(rowb[j], pc, tc);
                u64 x = pack2(pa * ta, pc * tc);
                #pragma unroll
                for (int k = 0; k < 11; k++) {
                    int o = j - k;
                    if (o >= 0 && o < 32) acc[o] = fma2(wp[k], x, acc[o]);
                }
            }
            #pragma unroll
            for (int o = 0; o < 32; o++) {
                float va, vb;
                unpack2(acc[o], va, vb);
                shC[(cb + o) * CSS + r0] = va;
                shC[(cb + o) * CSS + r1] = vb;
            }
        }
    }
    __syncthreads();

    // ---- Vertical pass + SSIM: thread = (column x, 8-row strip) ----
    const int x  = tid & 63;
    const int r0 = (tid >> 6) * 8;

    u64 mu[8];
    {
        const u64* col = shA + x * CS + r0;
        u64 wv[18];
        #pragma unroll
        for (int j = 0; j < 18; j++) wv[j] = col[j];
        #pragma unroll
        for (int o = 0; o < 8; o++) {
            u64 a = mul2(wp[0], wv[o]);
            #pragma unroll
            for (int k = 1; k < 11; k++) a = fma2(wp[k], wv[o + k], a);
            mu[o] = a;
        }
    }
    u64 sq[8];
    {
        const u64* col = shB + x * CS + r0;
        u64 wv[18];
        #pragma unroll
        for (int j = 0; j < 18; j++) wv[j] = col[j];
        #pragma unroll
        for (int o = 0; o < 8; o++) {
            u64 a = mul2(wp[0], wv[o]);
            #pragma unroll
            for (int k = 1; k < 11; k++) a = fma2(wp[k], wv[o + k], a);
            sq[o] = a;
        }
    }
    float cpt[8];
    {
        const float* col = shC + x * CSS + r0;
        float wc[18];
        #pragma unroll
        for (int j = 0; j < 18; j++) wc[j] = col[j];
        u64 pw[14];
        #pragma unroll
        for (int j = 0; j < 14; j++) pw[j] = pack2(wc[j], wc[j + 4]);
        #pragma unroll
        for (int o = 0; o < 4; o++) {
            u64 a = mul2(wp[0], pw[o]);
            #pragma unroll
            for (int k = 1; k < 11; k++) a = fma2(wp[k], pw[o + k], a);
            unpack2(a, cpt[o], cpt[o + 4]);   // outputs o and o+4
        }
    }

    const float C1 = 0.0001f;
    const float C2 = 0.0009f;
    float lsum = 0.0f;
    #pragma unroll
    for (int o = 0; o < 8; o++) {
        float mu1, mu2, ep2, et2;
        unpack2(mu[o], mu1, mu2);
        unpack2(sq[o], ep2, et2);
        float mu1sq = mu1 * mu1;
        float mu2sq = mu2 * mu2;
        float mu12  = mu1 * mu2;
        float s1  = ep2 - mu1sq;
        float s2  = et2 - mu2sq;
        float s12 = cpt[o] - mu12;
        float num = (2.0f * mu12 + C1) * (2.0f * s12 + C2);
        float den = (mu1sq + mu2sq + C1) * (s1 + s2 + C2);
        lsum += __fdividef(num, den);
    }

    // ---- Deterministic block reduction ----
    #pragma unroll
    for (int off = 16; off > 0; off >>= 1)
        lsum += __shfl_down_sync(0xffffffffu, lsum, off);
    if ((tid & 31) == 0) sred[tid >> 5] = lsum;
    __syncthreads();
    if (tid == 0) {
        float tot = 0.0f;
        #pragma unroll
        for (int wi = 0; wi < 8; wi++) tot += sred[wi];
        int bidx = (blockIdx.z * gridDim.y + blockIdx.y) * gridDim.x + blockIdx.x;
        g_partials[bidx] = tot;
    }
}

__global__ void __launch_bounds__(1024, 1)
ssim_finalize(float* __restrict__ out)
{
    __shared__ double shr[32];
    const int tid = threadIdx.x;
    double s = 0.0;
    for (int i = tid; i < NBLK; i += 1024)
        s += (double)g_partials[i];
    #pragma unroll
    for (int off = 16; off > 0; off >>= 1)
        s += __shfl_down_sync(0xffffffffu, s, off);
    if ((tid & 31) == 0) shr[tid >> 5] = s;
    __syncthreads();
    if (tid == 0) {
        double tot = 0.0;
        #pragma unroll
        for (int w = 0; w < 32; w++) tot += shr[w];
        out[0] = (float)(1.0 - tot / NTOT);
    }
}

extern "C" void kernel_launch(void* const* d_in, const int* in_sizes, int n_in,
                              void* d_out, int out_size)
{
    const float* pred = (const float*)d_in[0];
    const float* targ = (const float*)d_in[1];
    float* out = (float*)d_out;

    constexpr int smem_bytes =
        (LY * SPW + 2 * 64 * CS) * 8 + 64 * CSS * 4 + 8 * 4;
    cudaFuncSetAttribute(ssim_tile_kernel,
                         cudaFuncAttributeMaxDynamicSharedMemorySize, smem_bytes);

    dim3 grid(GX, GY, GZ);
    ssim_tile_kernel<<<grid, 256, smem_bytes>>>(pred, targ);
    ssim_finalize<<<1, 1024>>>(out);
}

// round 7
// speedup vs baseline: 1.1107x; 1.0019x over previous
#include <cuda_runtime.h>

// SSIM loss, pred/target [16,3,512,512] f32.
// Separable 11-tap Gaussian; fields packed 2-wide for fma.rn.f32x2:
//   stream A: (p, t)      packed in .x/.y
//   stream B: (p*p, t*t)  packed
//   stream C: p*t packed across row-pairs (r, r+21)
// Fused tile kernel (64x32 out, 74x42 loaded) + deterministic reduce.

#define TX   64
#define TY   32
#define LX   74
#define LY   42
#define SPW  75      // spt row stride (u64 units); lane-row delta 150 words -> conflict-free halves
#define CS   43      // shA/shB column stride (u64); lane-col delta 86 words -> conflict-free halves
#define CSS  45      // shC column stride (f32); delta 45 words (odd) -> conflict-free
#define GX   (512/TX)
#define GY   (512/TY)
#define GZ   48
#define NBLK (GX*GY*GZ)
#define NTOT 12582912.0

using u64 = unsigned long long;

__host__ __device__ constexpr float GWc(int k) {
    return (k == 0) ? 0.00102838f
         : (k == 1) ? 0.00759875f
         : (k == 2) ? 0.03600077f
         : (k == 3) ? 0.10936070f
         : (k == 4) ? 0.21300553f
         : (k == 5) ? 0.26601172f
         : (k == 6) ? 0.21300553f
         : (k == 7) ? 0.10936070f
         : (k == 8) ? 0.03600077f
         : (k == 9) ? 0.00759875f
         :            0.00102838f;
}

__device__ __forceinline__ u64 pack2(float lo, float hi) {
    u64 r; asm("mov.b64 %0, {%1,%2};" : "=l"(r) : "f"(lo), "f"(hi)); return r;
}
__device__ __forceinline__ void unpack2(u64 v, float& lo, float& hi) {
    asm("mov.b64 {%0,%1}, %2;" : "=f"(lo), "=f"(hi) : "l"(v));
}
__device__ __forceinline__ u64 fma2(u64 a, u64 b, u64 c) {
    u64 r; asm("fma.rn.f32x2 %0, %1, %2, %3;" : "=l"(r) : "l"(a), "l"(b), "l"(c)); return r;
}
__device__ __forceinline__ u64 mul2(u64 a, u64 b) {
    u64 r; asm("mul.rn.f32x2 %0, %1, %2;" : "=l"(r) : "l"(a), "l"(b)); return r;
}

__device__ float g_partials[NBLK];

__global__ void __launch_bounds__(256, 2)
ssim_tile_kernel(const float* __restrict__ pred, const float* __restrict__ targ)
{
    extern __shared__ char smem_raw[];
    u64*   spt  = (u64*)smem_raw;              // LY*SPW  (p,t) pairs
    u64*   shA  = spt + LY * SPW;              // 64*CS   hpass (mu1h, mu2h), [col][row]
    u64*   shB  = shA + 64 * CS;               // 64*CS   hpass (p2h, t2h),  [col][row]
    float* shC  = (float*)(shB + 64 * CS);     // 64*CSS  hpass pt, [col][row]
    float* sred = shC + 64 * CSS;              // 8 floats, reduction scratch

    const int tid = threadIdx.x;
    const int x0 = blockIdx.x * TX;
    const int y0 = blockIdx.y * TY;
    const int plane = blockIdx.z * (512 * 512);
    const float* pb = pred + plane;
    const float* tb = targ + plane;

    // ---- Load tile with halo, interleave (p,t) into u64 ----
    for (int i = tid; i < LY * LX; i += 256) {
        int r = i / LX;
        int c = i - r * LX;
        int gy = y0 - 5 + r;
        int gx = x0 - 5 + c;
        bool ok = ((unsigned)gy < 512u) && ((unsigned)gx < 512u);
        float pv = ok ? __ldg(pb + gy * 512 + gx) : 0.0f;
        float tv = ok ? __ldg(tb + gy * 512 + gx) : 0.0f;
        spt[r * SPW + c] = pack2(pv, tv);
    }
    __syncthreads();

    // packed weights (duplicated lanes); symmetric -> compiler CSEs to 6 live regs
    u64 wp[11];
    #pragma unroll
    for (int k = 0; k < 11; k++) wp[k] = pack2(GWc(k), GWc(k));

    // ---- Horizontal pass, warp-pure stream assignment ----
    // warps 0-2: stream A (84 tasks)   warps 3-5: stream B (84 tasks)
    // warps 6-7: stream C (42 tasks, row-pairs)
    const int w = tid >> 5;
    if (w < 3) {
        int t = tid;
        if (t < 84) {
            int half = (t >= 42); int r = t - half * 42; int cb = half * 32;
            const u64* row = spt + r * SPW + cb;
            u64 acc[32];
            #pragma unroll
            for (int o = 0; o < 32; o++) acc[o] = 0ull;
            #pragma unroll
            for (int j = 0; j < 42; j++) {
                u64 x = row[j];
                #pragma unroll
                for (int k = 0; k < 11; k++) {
                    int o = j - k;
                    if (o >= 0 && o < 32) acc[o] = fma2(wp[k], x, acc[o]);
                }
            }
            u64* out = shA + r;
            #pragma unroll
            for (int o = 0; o < 32; o++) out[(cb + o) * CS] = acc[o];
        }
    } else if (w < 6) {
        int t = tid - 96;
        if (t < 84) {
            int half = (t >= 42); int r = t - half * 42; int cb = half * 32;
            const u64* row = spt + r * SPW + cb;
            u64 acc[32];
            #pragma unroll
            for (int o = 0; o < 32; o++) acc[o] = 0ull;
            #pragma unroll
            for (int j = 0; j < 42; j++) {
                u64 x = row[j];
                x = mul2(x, x);
                #pragma unroll
                for (int k = 0; k < 11; k++) {
                    int o = j - k;
                    if (o >= 0 && o < 32) acc[o] = fma2(wp[k], x, acc[o]);
                }
            }
            u64* out = shB + r;
            #pragma unroll
            for (int o = 0; o < 32; o++) out[(cb + o) * CS] = acc[o];
        }
    } else {
        int t = tid - 192;
        if (t < 42) {
            int half = (t >= 21); int rp = t - half * 21; int cb = half * 32;
            int r0 = rp, r1 = rp + 21;
            const u64* rowa = spt + r0 * SPW + cb;
            const u64* rowb = spt + r1 * SPW + cb;
            u64 acc[32];
            #pragma unroll
            for (int o = 0; o < 32; o++) acc[o] = 0ull;
            #pragma unroll
            for (int j = 0; j < 42; j++) {
                float pa, ta, pc, tc;
                unpack2(rowa[j], pa, ta);
                unpack2(rowb[j], pc, tc);
                u64 x = pack2(pa * ta, pc * tc);
                #pragma unroll
                for (int k = 0; k < 11; k++) {
                    int o = j - k;
                    if (o >= 0 && o < 32) acc[o] = fma2(wp[k], x, acc[o]);
                }
            }
            #pragma unroll
            for (int o = 0; o < 32; o++) {
                float va, vb;
                unpack2(acc[o], va, vb);
                shC[(cb + o) * CSS + r0] = va;
                shC[(cb + o) * CSS + r1] = vb;
            }
        }
    }
    __syncthreads();

    // ---- Vertical pass + SSIM: thread = (column x, 8-row strip) ----
    const int x  = tid & 63;
    const int r0 = (tid >> 6) * 8;

    u64 mu[8];
    {
        const u64* col = shA + x * CS + r0;
        u64 wv[18];
        #pragma unroll
        for (int j = 0; j < 18; j++) wv[j] = col[j];
        #pragma unroll
        for (int o = 0; o < 8; o++) {
            u64 a = mul2(wp[0], wv[o]);
            #pragma unroll
            for (int k = 1; k < 11; k++) a = fma2(wp[k], wv[o + k], a);
            mu[o] = a;
        }
    }
    u64 sq[8];
    {
        const u64* col = shB + x * CS + r0;
        u64 wv[18];
        #pragma unroll
        for (int j = 0; j < 18; j++) wv[j] = col[j];
        #pragma unroll
        for (int o = 0; o < 8; o++) {
            u64 a = mul2(wp[0], wv[o]);
            #pragma unroll
            for (int k = 1; k < 11; k++) a = fma2(wp[k], wv[o + k], a);
            sq[o] = a;
        }
    }
    float cpt[8];
    {
        const float* col = shC + x * CSS + r0;
        float wc[18];
        #pragma unroll
        for (int j = 0; j < 18; j++) wc[j] = col[j];
        u64 pw[14];
        #pragma unroll
        for (int j = 0; j < 14; j++) pw[j] = pack2(wc[j], wc[j + 4]);
        #pragma unroll
        for (int o = 0; o < 4; o++) {
            u64 a = mul2(wp[0], pw[o]);
            #pragma unroll
            for (int k = 1; k < 11; k++) a = fma2(wp[k], pw[o + k], a);
            unpack2(a, cpt[o], cpt[o + 4]);   // outputs o and o+4
        }
    }

    const float C1 = 0.0001f;
    const float C2 = 0.0009f;
    float lsum = 0.0f;
    #pragma unroll
    for (int o = 0; o < 8; o++) {
        float mu1, mu2, ep2, et2;
        unpack2(mu[o], mu1, mu2);
        unpack2(sq[o], ep2, et2);
        float mu1sq = mu1 * mu1;
        float mu2sq = mu2 * mu2;
        float mu12  = mu1 * mu2;
        float s1  = ep2 - mu1sq;
        float s2  = et2 - mu2sq;
        float s12 = cpt[o] - mu12;
        float num = (2.0f * mu12 + C1) * (2.0f * s12 + C2);
        float den = (mu1sq + mu2sq + C1) * (s1 + s2 + C2);
        lsum += __fdividef(num, den);
    }

    // ---- Deterministic block reduction ----
    #pragma unroll
    for (int off = 16; off > 0; off >>= 1)
        lsum += __shfl_down_sync(0xffffffffu, lsum, off);
    if ((tid & 31) == 0) sred[tid >> 5] = lsum;
    __syncthreads();
    if (tid == 0) {
        float tot = 0.0f;
        #pragma unroll
        for (int wi = 0; wi < 8; wi++) tot += sred[wi];
        int bidx = (blockIdx.z * gridDim.y + blockIdx.y) * gridDim.x + blockIdx.x;
        g_partials[bidx] = tot;
    }
}

__global__ void __launch_bounds__(1024, 1)
ssim_finalize(float* __restrict__ out)
{
    __shared__ double shr[32];
    const int tid = threadIdx.x;
    double s = 0.0;
    for (int i = tid; i < NBLK; i += 1024)
        s += (double)g_partials[i];
    #pragma unroll
    for (int off = 16; off > 0; off >>= 1)
        s += __shfl_down_sync(0xffffffffu, s, off);
    if ((tid & 31) == 0) shr[tid >> 5] = s;
    __syncthreads();
    if (tid == 0) {
        double tot = 0.0;
        #pragma unroll
        for (int w = 0; w < 32; w++) tot += shr[w];
        out[0] = (float)(1.0 - tot / NTOT);
    }
}

extern "C" void kernel_launch(void* const* d_in, const int* in_sizes, int n_in,
                              void* d_out, int out_size)
{
    const float* pred = (const float*)d_in[0];
    const float* targ = (const float*)d_in[1];
    float* out = (float*)d_out;

    constexpr int smem_bytes =
        (LY * SPW + 2 * 64 * CS) * 8 + 64 * CSS * 4 + 8 * 4;
    cudaFuncSetAttribute(ssim_tile_kernel,
                         cudaFuncAttributeMaxDynamicSharedMemorySize, smem_bytes);

    dim3 grid(GX, GY, GZ);
    ssim_tile_kernel<<<grid, 256, smem_bytes>>>(pred, targ);
    ssim_finalize<<<1, 1024>>>(out);
}

// round 8
// speedup vs baseline: 1.1110x; 1.0003x over previous
#include <cuda_runtime.h>

// SSIM loss, pred/target [16,3,512,512] f32.
// Separable 11-tap Gaussian; fields packed 2-wide for fma.rn.f32x2:
//   stream A: (p, t)      packed in .x/.y
//   stream B: (p*p, t*t)  packed
//   stream C: p*t packed across row-pairs (r, r+21)
// Fused tile kernel (64x32 out, 74x42 loaded) + deterministic reduce.

#define TX   64
#define TY   32
#define LX   74
#define LY   42
#define SPW  75      // spt row stride (u64 units); lane-row delta 150 words -> conflict-free halves
#define CS   43      // shA/shB column stride (u64); lane-col delta 86 words -> conflict-free halves
#define CSS  45      // shC column stride (f32); delta 45 words (odd) -> conflict-free
#define GX   (512/TX)
#define GY   (512/TY)
#define GZ   48
#define NBLK (GX*GY*GZ)
#define NTOT 12582912.0

using u64 = unsigned long long;

__host__ __device__ constexpr float GWc(int k) {
    return (k == 0) ? 0.00102838f
         : (k == 1) ? 0.00759875f
         : (k == 2) ? 0.03600077f
         : (k == 3) ? 0.10936070f
         : (k == 4) ? 0.21300553f
         : (k == 5) ? 0.26601172f
         : (k == 6) ? 0.21300553f
         : (k == 7) ? 0.10936070f
         : (k == 8) ? 0.03600077f
         : (k == 9) ? 0.00759875f
         :            0.00102838f;
}

__device__ __forceinline__ u64 pack2(float lo, float hi) {
    u64 r; asm("mov.b64 %0, {%1,%2};" : "=l"(r) : "f"(lo), "f"(hi)); return r;
}
__device__ __forceinline__ void unpack2(u64 v, float& lo, float& hi) {
    asm("mov.b64 {%0,%1}, %2;" : "=f"(lo), "=f"(hi) : "l"(v));
}
__device__ __forceinline__ u64 fma2(u64 a, u64 b, u64 c) {
    u64 r; asm("fma.rn.f32x2 %0, %1, %2, %3;" : "=l"(r) : "l"(a), "l"(b), "l"(c)); return r;
}
__device__ __forceinline__ u64 mul2(u64 a, u64 b) {
    u64 r; asm("mul.rn.f32x2 %0, %1, %2;" : "=l"(r) : "l"(a), "l"(b)); return r;
}

__device__ float g_partials[NBLK];

__global__ void __launch_bounds__(256, 2)
ssim_tile_kernel(const float* __restrict__ pred, const float* __restrict__ targ)
{
    extern __shared__ char smem_raw[];
    u64*   spt  = (u64*)smem_raw;              // LY*SPW  (p,t) pairs
    u64*   shA  = spt + LY * SPW;              // 64*CS   hpass (mu1h, mu2h), [col][row]
    u64*   shB  = shA + 64 * CS;               // 64*CS   hpass (p2h, t2h),  [col][row]
    float* shC  = (float*)(shB + 64 * CS);     // 64*CSS  hpass pt, [col][row]
    float* sred = shC + 64 * CSS;              // 8 floats, reduction scratch

    const int tid = threadIdx.x;
    const int x0 = blockIdx.x * TX;
    const int y0 = blockIdx.y * TY;
    const int plane = blockIdx.z * (512 * 512);
    const float* pb = pred + plane;
    const float* tb = targ + plane;

    // ---- Load tile with halo, interleave (p,t) into u64 ----
    for (int i = tid; i < LY * LX; i += 256) {
        int r = i / LX;
        int c = i - r * LX;
        int gy = y0 - 5 + r;
        int gx = x0 - 5 + c;
        bool ok = ((unsigned)gy < 512u) && ((unsigned)gx < 512u);
        float pv = ok ? __ldg(pb + gy * 512 + gx) : 0.0f;
        float tv = ok ? __ldg(tb + gy * 512 + gx) : 0.0f;
        spt[r * SPW + c] = pack2(pv, tv);
    }
    __syncthreads();

    // packed weights (duplicated lanes); symmetric -> compiler CSEs to 6 live regs
    u64 wp[11];
    #pragma unroll
    for (int k = 0; k < 11; k++) wp[k] = pack2(GWc(k), GWc(k));

    // ---- Horizontal pass, warp-pure stream assignment ----
    // warps 0-2: stream A (84 tasks)   warps 3-5: stream B (84 tasks)
    // warps 6-7: stream C (42 tasks, row-pairs)
    const int w = tid >> 5;
    if (w < 3) {
        int t = tid;
        if (t < 84) {
            int half = (t >= 42); int r = t - half * 42; int cb = half * 32;
            const u64* row = spt + r * SPW + cb;
            u64 acc[32];
            #pragma unroll
            for (int o = 0; o < 32; o++) acc[o] = 0ull;
            #pragma unroll
            for (int j = 0; j < 42; j++) {
                u64 x = row[j];
                #pragma unroll
                for (int k = 0; k < 11; k++) {
                    int o = j - k;
                    if (o >= 0 && o < 32) acc[o] = fma2(wp[k], x, acc[o]);
                }
            }
            u64* out = shA + r;
            #pragma unroll
            for (int o = 0; o < 32; o++) out[(cb + o) * CS] = acc[o];
        }
    } else if (w < 6) {
        int t = tid - 96;
        if (t < 84) {
            int half = (t >= 42); int r = t - half * 42; int cb = half * 32;
            const u64* row = spt + r * SPW + cb;
            u64 acc[32];
            #pragma unroll
            for (int o = 0; o < 32; o++) acc[o] = 0ull;
            #pragma unroll
            for (int j = 0; j < 42; j++) {
                u64 x = row[j];
                x = mul2(x, x);
                #pragma unroll
                for (int k = 0; k < 11; k++) {
                    int o = j - k;
                    if (o >= 0 && o < 32) acc[o] = fma2(wp[k], x, acc[o]);
                }
            }
            u64* out = shB + r;
            #pragma unroll
            for (int o = 0; o < 32; o++) out[(cb + o) * CS] = acc[o];
        }
    } else {
        int t = tid - 192;
        if (t < 42) {
            int half = (t >= 21); int rp = t - half * 21; int cb = half * 32;
            int r0 = rp, r1 = rp + 21;
            const u64* rowa = spt + r0 * SPW + cb;
            const u64* rowb = spt + r1 * SPW + cb;
            u64 acc[32];
            #pragma unroll
            for (int o = 0; o < 32; o++) acc[o] = 0ull;
            #pragma unroll
            for (int j = 0; j < 42; j++) {
                float pa, ta, pc, tc;
                unpack2(rowa[j], pa, ta);
                unpack2(rowb[j], pc, tc);
                u64 x = pack2(pa * ta, pc * tc);
                #pragma unroll
                for (int k = 0; k < 11; k++) {
                    int o = j - k;
                    if (o >= 0 && o < 32) acc[o] = fma2(wp[k], x, acc[o]);
                }
            }
            #pragma unroll
            for (int o = 0; o < 32; o++) {
                float va, vb;
                unpack2(acc[o], va, vb);
                shC[(cb + o) * CSS + r0] = va;
                shC[(cb + o) * CSS + r1] = vb;
            }
        }
    }
    __syncthreads();

    // ---- Vertical pass + SSIM: thread = (column x, 8-row strip) ----
    const int x  = tid & 63;
    const int r0 = (tid >> 6) * 8;

    u64 mu[8];
    {
        const u64* col = shA + x * CS + r0;
        u64 wv[18];
        #pragma unroll
        for (int j = 0; j < 18; j++) wv[j] = col[j];
        #pragma unroll
        for (int o = 0; o < 8; o++) {
            u64 a = mul2(wp[0], wv[o]);
            #pragma unroll
            for (int k = 1; k < 11; k++) a = fma2(wp[k], wv[o + k], a);
            mu[o] = a;
        }
    }
    u64 sq[8];
    {
        const u64* col = shB + x * CS + r0;
        u64 wv[18];
        #pragma unroll
        for (int j = 0; j < 18; j++) wv[j] = col[j];
        #pragma unroll
        for (int o = 0; o < 8; o++) {
            u64 a = mul2(wp[0], wv[o]);
            #pragma unroll
            for (int k = 1; k < 11; k++) a = fma2(wp[k], wv[o + k], a);
            sq[o] = a;
        }
    }
    float cpt[8];
    {
        const float* col = shC + x * CSS + r0;
        float wc[18];
        #pragma unroll
        for (int j = 0; j < 18; j++) wc[j] = col[j];
        u64 pw[14];
        #pragma unroll
        for (int j = 0; j < 14; j++) pw[j] = pack2(wc[j], wc[j + 4]);
        #pragma unroll
        for (int o = 0; o < 4; o++) {
            u64 a = mul2(wp[0], pw[o]);
            #pragma unroll
            for (int k = 1; k < 11; k++) a = fma2(wp[k], pw[o + k], a);
            unpack2(a, cpt[o], cpt[o + 4]);   // outputs o and o+4
        }
    }

    const float C1 = 0.0001f;
    const float C2 = 0.0009f;
    float lsum = 0.0f;
    #pragma unroll
    for (int o = 0; o < 8; o++) {
        float mu1, mu2, ep2, et2;
        unpack2(mu[o], mu1, mu2);
        unpack2(sq[o], ep2, et2);
        float mu1sq = mu1 * mu1;
        float mu2sq = mu2 * mu2;
        float mu12  = mu1 * mu2;
        float s1  = ep2 - mu1sq;
        float s2  = et2 - mu2sq;
        float s12 = cpt[o] - mu12;
        float num = (2.0f * mu12 + C1) * (2.0f * s12 + C2);
        float den = (mu1sq + mu2sq + C1) * (s1 + s2 + C2);
        lsum += __fdividef(num, den);
    }

    // ---- Deterministic block reduction ----
    #pragma unroll
    for (int off = 16; off > 0; off >>= 1)
        lsum += __shfl_down_sync(0xffffffffu, lsum, off);
    if ((tid & 31) == 0) sred[tid >> 5] = lsum;
    __syncthreads();
    if (tid == 0) {
        float tot = 0.0f;
        #pragma unroll
        for (int wi = 0; wi < 8; wi++) tot += sred[wi];
        int bidx = (blockIdx.z * gridDim.y + blockIdx.y) * gridDim.x + blockIdx.x;
        g_partials[bidx] = tot;
    }
}

__global__ void __launch_bounds__(1024, 1)
ssim_finalize(float* __restrict__ out)
{
    __shared__ double shr[32];
    const int tid = threadIdx.x;
    double s = 0.0;
    for (int i = tid; i < NBLK; i += 1024)
        s += (double)g_partials[i];
    #pragma unroll
    for (int off = 16; off > 0; off >>= 1)
        s += __shfl_down_sync(0xffffffffu, s, off);
    if ((tid & 31) == 0) shr[tid >> 5] = s;
    __syncthreads();
    if (tid == 0) {
        double tot = 0.0;
        #pragma unroll
        for (int w = 0; w < 32; w++) tot += shr[w];
        out[0] = (float)(1.0 - tot / NTOT);
    }
}

extern "C" void kernel_launch(void* const* d_in, const int* in_sizes, int n_in,
                              void* d_out, int out_size)
{
    const float* pred = (const float*)d_in[0];
    const float* targ = (const float*)d_in[1];
    float* out = (float*)d_out;

    constexpr int smem_bytes =
        (LY * SPW + 2 * 64 * CS) * 8 + 64 * CSS * 4 + 8 * 4;
    cudaFuncSetAttribute(ssim_tile_kernel,
                         cudaFuncAttributeMaxDynamicSharedMemorySize, smem_bytes);

    dim3 grid(GX, GY, GZ);
    ssim_tile_kernel<<<grid, 256, smem_bytes>>>(pred, targ);
    ssim_finalize<<<1, 1024>>>(out);
}